// round 10
// baseline (speedup 1.0000x reference)
#include <cuda_runtime.h>
#include <cuda_bf16.h>
#include <math.h>
#include <stdint.h>

#define T_TOK 4096
#define H_DIM 2048
#define I_DIM 6144

// ================= device scratch (static — no runtime alloc) =================
__device__ __align__(128) int8_t  g_xqh[(size_t)T_TOK * H_DIM];   // q>>8 (s8)
__device__ __align__(128) uint8_t g_xql[(size_t)T_TOK * H_DIM];   // q&255 (u8)
__device__ __align__(128) int8_t  g_wu[(size_t)I_DIM * H_DIM];    // int4 codes (s8)
__device__ __align__(128) int8_t  g_wg[(size_t)I_DIM * H_DIM];
__device__ __align__(128) int8_t  g_wd[(size_t)H_DIM * I_DIM];
__device__ __align__(128) float   g_wsu[(size_t)(H_DIM / 32) * I_DIM];  // [blk][n]
__device__ __align__(128) float   g_wsg[(size_t)(H_DIM / 32) * I_DIM];
__device__ __align__(128) float   g_wsd[(size_t)(I_DIM / 32) * H_DIM];
__device__ __align__(128) int8_t  g_mqh[(size_t)T_TOK * I_DIM];
__device__ __align__(128) uint8_t g_mql[(size_t)T_TOK * I_DIM];
__device__ __align__(128) float   g_up[(size_t)T_TOK * I_DIM];
__device__ __align__(128) float   g_gate[(size_t)T_TOK * I_DIM];
__device__ unsigned g_absmax[8]; // 0=x 1=up 2=gate 3=act 4=mid

#define MAGIC_I 0x4B400000
#define MAGIC_F 12582912.f

// ================= PTX helpers =================
__device__ __forceinline__ uint32_t smem_u32(const void* p) {
    uint32_t a;
    asm("{ .reg .u64 t; cvta.to.shared.u64 t, %1; cvt.u32.u64 %0, t; }" : "=r"(a) : "l"(p));
    return a;
}
__device__ __forceinline__ void cp16(uint32_t dst, const void* src) {
    asm volatile("cp.async.cg.shared.global [%0], [%1], 16;" :: "r"(dst), "l"(src));
}
#define CP_COMMIT() asm volatile("cp.async.commit_group;" ::: "memory")

#define LDSM4(r, addr) \
    asm volatile("ldmatrix.sync.aligned.m8n8.x4.shared.b16 {%0,%1,%2,%3}, [%4];" \
        : "=r"((r)[0]), "=r"((r)[1]), "=r"((r)[2]), "=r"((r)[3]) : "r"(addr))

// s8 x s8 MMA, accumulator initialized with magic bits (result bits = float(M + d))
#define MMA_S8_MG(d, a, b0, b1) \
    asm volatile("mma.sync.aligned.m16n8k32.row.col.s32.s8.s8.s32 " \
        "{%0,%1,%2,%3},{%4,%5,%6,%7},{%8,%9},{%10,%10,%10,%10};" \
        : "=r"((d)[0]), "=r"((d)[1]), "=r"((d)[2]), "=r"((d)[3]) \
        : "r"((a)[0]), "r"((a)[1]), "r"((a)[2]), "r"((a)[3]), \
          "r"(b0), "r"(b1), "r"(MAGIC_I))

// u8 x s8 MMA, magic-initialized accumulator
#define MMA_U8_MG(d, a, b0, b1) \
    asm volatile("mma.sync.aligned.m16n8k32.row.col.s32.u8.s8.s32 " \
        "{%0,%1,%2,%3},{%4,%5,%6,%7},{%8,%9},{%10,%10,%10,%10};" \
        : "=r"((d)[0]), "=r"((d)[1]), "=r"((d)[2]), "=r"((d)[3]) \
        : "r"((a)[0]), "r"((a)[1]), "r"((a)[2]), "r"((a)[3]), \
          "r"(b0), "r"(b1), "r"(MAGIC_I))

__device__ __forceinline__ float get_scale(int slot, float qmax) {
    return fmaxf(__uint_as_float(g_absmax[slot]) / qmax, 1e-12f);
}
__device__ __forceinline__ void warp_atomic_absmax(int slot, float v) {
    #pragma unroll
    for (int o = 16; o; o >>= 1) v = fmaxf(v, __shfl_xor_sync(0xffffffffu, v, o));
    if ((threadIdx.x & 31) == 0) atomicMax(&g_absmax[slot], __float_as_uint(v));
}
__device__ __forceinline__ uint32_t pack4(int b0, int b1, int b2, int b3) {
    return (uint32_t)(b0 & 0xFF) | ((uint32_t)(b1 & 0xFF) << 8) |
           ((uint32_t)(b2 & 0xFF) << 16) | ((uint32_t)(b3 & 0xFF) << 24);
}
__device__ __forceinline__ float qdq_fast(float v, float s, float inv, float lo, float hi) {
    float q = rintf(v * inv);
    return fminf(fmaxf(q, lo), hi) * s;
}

// ================= elementwise kernels =================
__global__ void k_zero() { if (threadIdx.x < 8) g_absmax[threadIdx.x] = 0u; }

__global__ void k_absmax4(const float4* __restrict__ x, size_t n4, int slot) {
    size_t i = (size_t)blockIdx.x * blockDim.x + threadIdx.x;
    size_t st = (size_t)gridDim.x * blockDim.x;
    float m = 0.f;
    for (; i < n4; i += st) {
        float4 v = x[i];
        m = fmaxf(m, fmaxf(fmaxf(fabsf(v.x), fabsf(v.y)), fmaxf(fabsf(v.z), fabsf(v.w))));
    }
    warp_atomic_absmax(slot, m);
}

// quantize fp32 -> exact int16 code, split into s8 hi / u8 lo planes. 16 elems/thread.
__global__ void k_split_i8(const float4* __restrict__ in, uint4* __restrict__ oh,
                           uint4* __restrict__ ol, size_t n16, int slot) {
    float s = get_scale(slot, 32767.f);
    float inv = 1.f / s;
    size_t i = (size_t)blockIdx.x * blockDim.x + threadIdx.x;
    size_t st = (size_t)gridDim.x * blockDim.x;
    for (; i < n16; i += st) {
        int iq[16];
        #pragma unroll
        for (int w = 0; w < 4; w++) {
            float4 v = in[4 * i + w];
            float f[4] = {v.x, v.y, v.z, v.w};
            #pragma unroll
            for (int e = 0; e < 4; e++) {
                float q = rintf(f[e] * inv);
                q = fminf(fmaxf(q, -32768.f), 32767.f);
                iq[4 * w + e] = (int)q;
            }
        }
        uint32_t hw[4], lw[4];
        #pragma unroll
        for (int w = 0; w < 4; w++) {
            hw[w] = pack4(iq[4*w] >> 8, iq[4*w+1] >> 8, iq[4*w+2] >> 8, iq[4*w+3] >> 8);
            lw[w] = pack4(iq[4*w], iq[4*w+1], iq[4*w+2], iq[4*w+3]);
        }
        oh[i] = make_uint4(hw[0], hw[1], hw[2], hw[3]);
        ol[i] = make_uint4(lw[0], lw[1], lw[2], lw[3]);
    }
}

// LPBQ weight: int4 code (s8 storage) + per-block scale, scale stored transposed [b][n]
__global__ void k_dqw_i8(const float* __restrict__ w, uint4* __restrict__ oq,
                         float* __restrict__ wsT, int N, int K) {
    int kb = K / 32;
    size_t nblk = (size_t)N * kb;
    size_t i = (size_t)blockIdx.x * blockDim.x + threadIdx.x;
    size_t st = (size_t)gridDim.x * blockDim.x;
    for (; i < nblk; i += st) {
        int n = (int)(i / kb);
        int b = (int)(i % kb);
        const float4* p = (const float4*)(w + (size_t)n * K + b * 32);
        float4 v[8];
        float m = 0.f;
        #pragma unroll
        for (int j = 0; j < 8; j++) {
            v[j] = p[j];
            m = fmaxf(m, fmaxf(fmaxf(fabsf(v[j].x), fabsf(v[j].y)),
                               fmaxf(fabsf(v[j].z), fabsf(v[j].w))));
        }
        float s = fmaxf(m / 7.0f, 1e-12f);
        float inv = 1.f / s;
        uint32_t qw[8];
        #pragma unroll
        for (int j = 0; j < 8; j++) {
            float f[4] = {v[j].x, v[j].y, v[j].z, v[j].w};
            int q[4];
            #pragma unroll
            for (int e = 0; e < 4; e++) {
                float r = rintf(f[e] * inv);
                r = fminf(fmaxf(r, -8.f), 7.f);
                q[e] = (int)r;
            }
            qw[j] = pack4(q[0], q[1], q[2], q[3]);
        }
        uint4* dst = oq + ((size_t)n * K + b * 32) / 16;
        dst[0] = make_uint4(qw[0], qw[1], qw[2], qw[3]);
        dst[1] = make_uint4(qw[4], qw[5], qw[6], qw[7]);
        wsT[(size_t)b * N + n] = s;
    }
}

// P4: up_q = qdq(up,s1); act = silu(up_q) -> g_up; amax|act| -> 3
__global__ void k_p4(size_t n4) {
    float s1 = get_scale(1, 32767.f);
    float inv1 = 1.f / s1;
    float4* up = (float4*)g_up;
    size_t i = (size_t)blockIdx.x * blockDim.x + threadIdx.x;
    size_t st = (size_t)gridDim.x * blockDim.x;
    float m = 0.f;
    for (; i < n4; i += st) {
        float4 u = up[i];
        float f[4] = {u.x, u.y, u.z, u.w};
        #pragma unroll
        for (int e = 0; e < 4; e++) {
            float uq = qdq_fast(f[e], s1, inv1, -32768.f, 32767.f);
            float a = uq * __frcp_rn(1.f + __expf(-uq));
            f[e] = a;
            m = fmaxf(m, fabsf(a));
        }
        up[i] = make_float4(f[0], f[1], f[2], f[3]);
    }
    warp_atomic_absmax(3, m);
}

// P5: gate_q = qdq(gate,s2); act_q = qdq(act,s3); mid = gate_q*act_q -> g_gate; amax -> 4
__global__ void k_p5(size_t n4) {
    float s2 = get_scale(2, 32767.f);
    float inv2 = 1.f / s2;
    float s3 = get_scale(3, 32767.f);
    float inv3 = 1.f / s3;
    const float4* up = (const float4*)g_up;
    float4* gt = (float4*)g_gate;
    size_t i = (size_t)blockIdx.x * blockDim.x + threadIdx.x;
    size_t st = (size_t)gridDim.x * blockDim.x;
    float m = 0.f;
    for (; i < n4; i += st) {
        float4 a = up[i];
        float4 g = gt[i];
        float fa[4] = {a.x, a.y, a.z, a.w};
        float fg[4] = {g.x, g.y, g.z, g.w};
        #pragma unroll
        for (int e = 0; e < 4; e++) {
            float gq = qdq_fast(fg[e], s2, inv2, -32768.f, 32767.f);
            float aq = qdq_fast(fa[e], s3, inv3, -32768.f, 32767.f);
            float mv = gq * aq;
            fg[e] = mv;
            m = fmaxf(m, fabsf(mv));
        }
        gt[i] = make_float4(fg[0], fg[1], fg[2], fg[3]);
    }
    warp_atomic_absmax(4, m);
}

// ================= int8 IMMA GEMM (exact, magic fixup, no cvt) =================
// C[M,N] = s_a * sum_blk s_w[n][blk] * (256*dh_blk + dl_blk)
// dh = s8(hi) x s4 codes, dl = u8(lo) x s4 codes; both IMMAs independent with
// magic-initialized accumulators; fixup = 2 FADD + 2 FFMA per element (FMA pipe only).
// CTA 128x128, BK=64 (2 scale blocks), 4-stage cp.async, 8 warps, 1 CTA/SM.
#define BM 128
#define BN 128
#define BK 64
#define STAGES 4
#define TILE_B 8192
#define STAGE_BYTES (3 * TILE_B)
#define GEMM_SMEM (STAGES * STAGE_BYTES)  // 98304

__device__ __forceinline__ uint32_t swz(int r, int c) {
    return (uint32_t)(((r >> 1) << 7) + (((((r & 1) << 2) + c) ^ ((r >> 1) & 7)) << 4));
}

__device__ __forceinline__ void load_stage_i8(
    int c, int m0, int n0, int K, int tid, uint32_t sbase,
    const int8_t* __restrict__ Ah, const uint8_t* __restrict__ Al,
    const int8_t* __restrict__ Bw) {
    int kk = c * BK;
    uint32_t st = sbase + (uint32_t)(c % STAGES) * STAGE_BYTES;
    #pragma unroll
    for (int t = 0; t < 2; t++) {
        int id = tid + t * 256;
        int r = id >> 2, ch = id & 3;
        uint32_t so = swz(r, ch);
        size_t goA = (size_t)(m0 + r) * K + kk + ch * 16;
        size_t goB = (size_t)(n0 + r) * K + kk + ch * 16;
        cp16(st + so, Ah + goA);
        cp16(st + TILE_B + so, Al + goA);
        cp16(st + 2 * TILE_B + so, Bw + goB);
    }
    CP_COMMIT();
}

__global__ void __launch_bounds__(256, 1)
k_gemm_i8(const int8_t* __restrict__ Ah, const uint8_t* __restrict__ Al,
          const int8_t* __restrict__ Bw, const float* __restrict__ WsT,
          float* __restrict__ C, int N, int K, int slot_in, int slot_out) {
    extern __shared__ char smem[];
    const uint32_t sbase = smem_u32(smem);
    const int tid = threadIdx.x, wid = tid >> 5, lane = tid & 31;
    const int wm = wid >> 2, wn = wid & 3;       // 2 x 4 warp grid, warp tile 64x32
    const int m0 = blockIdx.y * BM, n0 = blockIdx.x * BN;
    const int chunks = K / BK;

    float facc[4][4][4];
    #pragma unroll
    for (int i = 0; i < 4; i++)
        #pragma unroll
        for (int j = 0; j < 4; j++)
            #pragma unroll
            for (int e = 0; e < 4; e++) facc[i][j][e] = 0.f;

    const int a_ro = (lane & 7) + ((lane & 8) ? 8 : 0);
    const int a_co = (lane & 16) ? 1 : 0;
    const int b_ro = (lane & 7) + ((lane & 16) ? 8 : 0);
    const int b_co = (lane & 8) ? 1 : 0;

    load_stage_i8(0, m0, n0, K, tid, sbase, Ah, Al, Bw);
    load_stage_i8(1, m0, n0, K, tid, sbase, Ah, Al, Bw);
    load_stage_i8(2, m0, n0, K, tid, sbase, Ah, Al, Bw);

    for (int c = 0; c < chunks; ++c) {
        if (c + 2 < chunks)      asm volatile("cp.async.wait_group 2;" ::: "memory");
        else if (c + 1 < chunks) asm volatile("cp.async.wait_group 1;" ::: "memory");
        else                     asm volatile("cp.async.wait_group 0;" ::: "memory");
        __syncthreads();
        if (c + STAGES - 1 < chunks)
            load_stage_i8(c + STAGES - 1, m0, n0, K, tid, sbase, Ah, Al, Bw);

        uint32_t st = sbase + (uint32_t)(c % STAGES) * STAGE_BYTES;
        uint32_t sAh = st, sAl = st + TILE_B, sB = st + 2 * TILE_B;

        #pragma unroll
        for (int kb = 0; kb < 2; kb++) {
            int bglob = c * 2 + kb;
            const float* wsr = WsT + (size_t)bglob * N + n0 + wn * 32 + (lane & 3) * 2;
            float2 sc[4];
            #pragma unroll
            for (int j = 0; j < 4; j++) sc[j] = __ldg((const float2*)(wsr + j * 8));

            uint32_t bf[8];
            #pragma unroll
            for (int j2 = 0; j2 < 2; j2++) {
                int r = wn * 32 + j2 * 16 + b_ro;
                LDSM4(&bf[j2 * 4], sB + swz(r, kb * 2 + b_co));
            }
            uint32_t afh[4][4], afl[4][4];
            #pragma unroll
            for (int i = 0; i < 4; i++) {
                int r = wm * 64 + i * 16 + a_ro;
                LDSM4(afh[i], sAh + swz(r, kb * 2 + a_co));
                LDSM4(afl[i], sAl + swz(r, kb * 2 + a_co));
            }
            #pragma unroll
            for (int i = 0; i < 4; i++)
                #pragma unroll
                for (int j = 0; j < 4; j++) {
                    int dh[4], dl[4];
                    uint32_t b0 = bf[(j >> 1) * 4 + (j & 1) * 2];
                    uint32_t b1 = bf[(j >> 1) * 4 + (j & 1) * 2 + 1];
                    MMA_S8_MG(dh, afh[i], b0, b1);
                    MMA_U8_MG(dl, afl[i], b0, b1);
                    #pragma unroll
                    for (int e = 0; e < 4; e++) {
                        float fh = __int_as_float(dh[e]) - MAGIC_F;  // exact dh
                        float fl = __int_as_float(dl[e]) - MAGIC_F;  // exact dl
                        float u = fmaf(256.f, fh, fl);               // exact (<2^24)
                        float s = (e & 1) ? sc[j].y : sc[j].x;
                        facc[i][j][e] = fmaf(u, s, facc[i][j][e]);
                    }
                }
        }
    }

    float s = get_scale(slot_in, 32767.f);
    const int g = lane >> 2, q = lane & 3;
    float mx = 0.f;
    #pragma unroll
    for (int i = 0; i < 4; i++) {
        #pragma unroll
        for (int j = 0; j < 4; j++) {
            int row = m0 + wm * 64 + i * 16 + g;
            int col = n0 + wn * 32 + j * 8 + q * 2;
            float v0 = facc[i][j][0] * s, v1 = facc[i][j][1] * s;
            float v2 = facc[i][j][2] * s, v3 = facc[i][j][3] * s;
            *(float2*)&C[(size_t)row * N + col] = make_float2(v0, v1);
            *(float2*)&C[(size_t)(row + 8) * N + col] = make_float2(v2, v3);
            mx = fmaxf(mx, fmaxf(fmaxf(fabsf(v0), fabsf(v1)), fmaxf(fabsf(v2), fabsf(v3))));
        }
    }
    if (slot_out >= 0) warp_atomic_absmax(slot_out, mx);
}

// ================= host =================
extern "C" void kernel_launch(void* const* d_in, const int* in_sizes, int n_in,
                              void* d_out, int out_size) {
    const float* x      = (const float*)d_in[0];
    const float* w_gate = (const float*)d_in[1];
    const float* w_up   = (const float*)d_in[2];
    const float* w_down = (const float*)d_in[3];
    float* out = (float*)d_out;

    void *p_xqh, *p_xql, *p_wu, *p_wg, *p_wd, *p_wsu, *p_wsg, *p_wsd;
    void *p_mqh, *p_mql, *p_up, *p_gate;
    cudaGetSymbolAddress(&p_xqh, g_xqh); cudaGetSymbolAddress(&p_xql, g_xql);
    cudaGetSymbolAddress(&p_wu, g_wu);   cudaGetSymbolAddress(&p_wg, g_wg);
    cudaGetSymbolAddress(&p_wd, g_wd);
    cudaGetSymbolAddress(&p_wsu, g_wsu); cudaGetSymbolAddress(&p_wsg, g_wsg);
    cudaGetSymbolAddress(&p_wsd, g_wsd);
    cudaGetSymbolAddress(&p_mqh, g_mqh); cudaGetSymbolAddress(&p_mql, g_mql);
    cudaGetSymbolAddress(&p_up, g_up);   cudaGetSymbolAddress(&p_gate, g_gate);

    static bool once = false;
    if (!once) {
        cudaFuncSetAttribute(k_gemm_i8, cudaFuncAttributeMaxDynamicSharedMemorySize, GEMM_SMEM);
        once = true;
    }

    const int GS = 1184;
    const size_t nx4  = (size_t)T_TOK * H_DIM / 4;
    const size_t nx16 = (size_t)T_TOK * H_DIM / 16;
    const size_t nti4 = (size_t)T_TOK * I_DIM / 4;
    const size_t nti16 = (size_t)T_TOK * I_DIM / 16;

    k_zero<<<1, 32>>>();
    k_absmax4<<<GS, 256>>>((const float4*)x, nx4, 0);
    k_split_i8<<<GS, 256>>>((const float4*)x, (uint4*)p_xqh, (uint4*)p_xql, nx16, 0);
    k_dqw_i8<<<GS, 256>>>(w_up,   (uint4*)p_wu, (float*)p_wsu, I_DIM, H_DIM);
    k_dqw_i8<<<GS, 256>>>(w_gate, (uint4*)p_wg, (float*)p_wsg, I_DIM, H_DIM);
    k_dqw_i8<<<GS, 256>>>(w_down, (uint4*)p_wd, (float*)p_wsd, H_DIM, I_DIM);

    dim3 g1(I_DIM / BN, T_TOK / BM);   // 48 x 32
    k_gemm_i8<<<g1, 256, GEMM_SMEM>>>((const int8_t*)p_xqh, (const uint8_t*)p_xql,
                                      (const int8_t*)p_wu, (const float*)p_wsu,
                                      (float*)p_up, I_DIM, H_DIM, 0, 1);
    k_gemm_i8<<<g1, 256, GEMM_SMEM>>>((const int8_t*)p_xqh, (const uint8_t*)p_xql,
                                      (const int8_t*)p_wg, (const float*)p_wsg,
                                      (float*)p_gate, I_DIM, H_DIM, 0, 2);
    k_p4<<<GS, 256>>>(nti4);
    k_p5<<<GS, 256>>>(nti4);
    k_split_i8<<<GS, 256>>>((const float4*)p_gate, (uint4*)p_mqh, (uint4*)p_mql, nti16, 4);

    dim3 g3(H_DIM / BN, T_TOK / BM);   // 16 x 32
    k_gemm_i8<<<g3, 256, GEMM_SMEM>>>((const int8_t*)p_mqh, (const uint8_t*)p_mql,
                                      (const int8_t*)p_wd, (const float*)p_wsd,
                                      out, H_DIM, I_DIM, 4, -1);
}

// round 11
// speedup vs baseline: 2.7047x; 2.7047x over previous
#include <cuda_runtime.h>
#include <cuda_bf16.h>
#include <math.h>
#include <stdint.h>

#define T_TOK 4096
#define H_DIM 2048
#define I_DIM 6144

// ================= device scratch (static — no runtime alloc) =================
__device__ __align__(128) __nv_bfloat16 g_xh[(size_t)T_TOK * H_DIM];  // (q>>8)*256
__device__ __align__(128) __nv_bfloat16 g_xl[(size_t)T_TOK * H_DIM];  // q&255
__device__ __align__(128) __nv_bfloat16 g_wu[(size_t)I_DIM * H_DIM];  // int4 codes as bf16
__device__ __align__(128) __nv_bfloat16 g_wg[(size_t)I_DIM * H_DIM];
__device__ __align__(128) __nv_bfloat16 g_wd[(size_t)H_DIM * I_DIM];
__device__ __align__(128) float g_wsu[(size_t)(H_DIM / 32) * I_DIM];  // [block][n]
__device__ __align__(128) float g_wsg[(size_t)(H_DIM / 32) * I_DIM];
__device__ __align__(128) float g_wsd[(size_t)(I_DIM / 32) * H_DIM];
__device__ __align__(128) __nv_bfloat16 g_mh[(size_t)T_TOK * I_DIM];
__device__ __align__(128) __nv_bfloat16 g_ml[(size_t)T_TOK * I_DIM];
__device__ __align__(128) float g_up[(size_t)T_TOK * I_DIM];    // up raw -> act (in place)
__device__ __align__(128) float g_gate[(size_t)T_TOK * I_DIM];  // gate raw -> mid
__device__ unsigned g_absmax[8]; // 0=x 1=up 2=gate 3=act 4=mid

// ================= PTX helpers =================
__device__ __forceinline__ uint32_t smem_u32(const void* p) {
    uint32_t a;
    asm("{ .reg .u64 t; cvta.to.shared.u64 t, %1; cvt.u32.u64 %0, t; }" : "=r"(a) : "l"(p));
    return a;
}
__device__ __forceinline__ void cp16(uint32_t dst, const void* src) {
    asm volatile("cp.async.cg.shared.global [%0], [%1], 16;" :: "r"(dst), "l"(src));
}
#define CP_COMMIT() asm volatile("cp.async.commit_group;" ::: "memory")

#define LDSM4(r, addr) \
    asm volatile("ldmatrix.sync.aligned.m8n8.x4.shared.b16 {%0,%1,%2,%3}, [%4];" \
        : "=r"((r)[0]), "=r"((r)[1]), "=r"((r)[2]), "=r"((r)[3]) : "r"(addr))

// P = A*B + 0
#define MMA_BF16_ZC(d, a, b0, b1) \
    asm volatile("mma.sync.aligned.m16n8k16.row.col.f32.bf16.bf16.f32 " \
        "{%0,%1,%2,%3},{%4,%5,%6,%7},{%8,%9},{%10,%10,%10,%10};" \
        : "=f"((d)[0]), "=f"((d)[1]), "=f"((d)[2]), "=f"((d)[3]) \
        : "r"((a)[0]), "r"((a)[1]), "r"((a)[2]), "r"((a)[3]), \
          "r"(b0), "r"(b1), "f"(0.f))

// P += A*B
#define MMA_BF16_ACC(d, a, b0, b1) \
    asm volatile("mma.sync.aligned.m16n8k16.row.col.f32.bf16.bf16.f32 " \
        "{%0,%1,%2,%3},{%4,%5,%6,%7},{%8,%9},{%0,%1,%2,%3};" \
        : "+f"((d)[0]), "+f"((d)[1]), "+f"((d)[2]), "+f"((d)[3]) \
        : "r"((a)[0]), "r"((a)[1]), "r"((a)[2]), "r"((a)[3]), "r"(b0), "r"(b1))

__device__ __forceinline__ float get_scale(int slot, float qmax) {
    return fmaxf(__uint_as_float(g_absmax[slot]) / qmax, 1e-12f);
}
__device__ __forceinline__ void warp_atomic_absmax(int slot, float v) {
    #pragma unroll
    for (int o = 16; o; o >>= 1) v = fmaxf(v, __shfl_xor_sync(0xffffffffu, v, o));
    if ((threadIdx.x & 31) == 0) atomicMax(&g_absmax[slot], __float_as_uint(v));
}
__device__ __forceinline__ uint32_t pack_bf2f(float a, float b) {
    __nv_bfloat162 t{__float2bfloat16_rn(a), __float2bfloat16_rn(b)};
    return *(uint32_t*)&t;
}
__device__ __forceinline__ float qdq_fast(float v, float s, float inv, float lo, float hi) {
    float q = rintf(v * inv);
    return fminf(fmaxf(q, lo), hi) * s;
}
__device__ __forceinline__ float silu_of_qdq(float v, float s1, float inv1) {
    float uq = qdq_fast(v, s1, inv1, -32768.f, 32767.f);
    return uq * __frcp_rn(1.f + __expf(-uq));
}

// ================= elementwise kernels =================
__global__ void k_zero() { if (threadIdx.x < 8) g_absmax[threadIdx.x] = 0u; }

__global__ void k_absmax4(const float4* __restrict__ x, size_t n4, int slot) {
    size_t i = (size_t)blockIdx.x * blockDim.x + threadIdx.x;
    size_t st = (size_t)gridDim.x * blockDim.x;
    float m = 0.f;
    for (; i < n4; i += st) {
        float4 v = x[i];
        m = fmaxf(m, fmaxf(fmaxf(fabsf(v.x), fabsf(v.y)), fmaxf(fabsf(v.z), fabsf(v.w))));
    }
    warp_atomic_absmax(slot, m);
}

// quantize fp32 -> int16 code -> exact bf16 planes: hi=(q>>8)*256, lo=q&255. 8 elems/thread.
__global__ void k_split_bf16(const float4* __restrict__ in, uint4* __restrict__ oh,
                             uint4* __restrict__ ol, size_t n8, int slot) {
    float s = get_scale(slot, 32767.f);
    float inv = 1.f / s;
    size_t i = (size_t)blockIdx.x * blockDim.x + threadIdx.x;
    size_t st = (size_t)gridDim.x * blockDim.x;
    for (; i < n8; i += st) {
        float4 v0 = in[2 * i], v1 = in[2 * i + 1];
        float f[8] = {v0.x, v0.y, v0.z, v0.w, v1.x, v1.y, v1.z, v1.w};
        float fh[8], fl[8];
        #pragma unroll
        for (int e = 0; e < 8; e++) {
            float q = rintf(f[e] * inv);
            q = fminf(fmaxf(q, -32768.f), 32767.f);
            int iq = (int)q;
            int ih = iq >> 8;
            fh[e] = (float)(ih << 8);       // multiple of 256, exact bf16
            fl[e] = (float)(iq & 255);      // 0..255, exact bf16
        }
        oh[i] = make_uint4(pack_bf2f(fh[0], fh[1]), pack_bf2f(fh[2], fh[3]),
                           pack_bf2f(fh[4], fh[5]), pack_bf2f(fh[6], fh[7]));
        ol[i] = make_uint4(pack_bf2f(fl[0], fl[1]), pack_bf2f(fl[2], fl[3]),
                           pack_bf2f(fl[4], fl[5]), pack_bf2f(fl[6], fl[7]));
    }
}

// LPBQ weight: int4 codes stored as bf16 (exact) + per-block scale transposed [b][n]
__global__ void k_dqw_bf16(const float* __restrict__ w, uint4* __restrict__ oq,
                           float* __restrict__ wsT, int N, int K) {
    int kb = K / 32;
    size_t nblk = (size_t)N * kb;
    size_t i = (size_t)blockIdx.x * blockDim.x + threadIdx.x;
    size_t st = (size_t)gridDim.x * blockDim.x;
    for (; i < nblk; i += st) {
        int n = (int)(i / kb);
        int b = (int)(i % kb);
        const float4* p = (const float4*)(w + (size_t)n * K + b * 32);
        float4 v[8];
        float m = 0.f;
        #pragma unroll
        for (int j = 0; j < 8; j++) {
            v[j] = p[j];
            m = fmaxf(m, fmaxf(fmaxf(fabsf(v[j].x), fabsf(v[j].y)),
                               fmaxf(fabsf(v[j].z), fabsf(v[j].w))));
        }
        float s = fmaxf(m / 7.0f, 1e-12f);
        float inv = 1.f / s;
        uint32_t cw[16];
        #pragma unroll
        for (int j = 0; j < 8; j++) {
            float f[4] = {v[j].x, v[j].y, v[j].z, v[j].w};
            float q[4];
            #pragma unroll
            for (int e = 0; e < 4; e++)
                q[e] = fminf(fmaxf(rintf(f[e] * inv), -8.f), 7.f);
            cw[2 * j]     = pack_bf2f(q[0], q[1]);
            cw[2 * j + 1] = pack_bf2f(q[2], q[3]);
        }
        uint4* dst = oq + ((size_t)n * K + b * 32) / 8;
        #pragma unroll
        for (int j = 0; j < 4; j++)
            dst[j] = make_uint4(cw[4 * j], cw[4 * j + 1], cw[4 * j + 2], cw[4 * j + 3]);
        wsT[(size_t)b * N + n] = s;
    }
}

// P5: gate_q = qdq(gate,s2); act_q = qdq(act,s3); mid = gate_q*act_q -> g_gate; amax -> 4
__global__ void k_p5(size_t n4) {
    float s2 = get_scale(2, 32767.f);
    float inv2 = 1.f / s2;
    float s3 = get_scale(3, 32767.f);
    float inv3 = 1.f / s3;
    const float4* up = (const float4*)g_up;
    float4* gt = (float4*)g_gate;
    size_t i = (size_t)blockIdx.x * blockDim.x + threadIdx.x;
    size_t st = (size_t)gridDim.x * blockDim.x;
    float m = 0.f;
    for (; i < n4; i += st) {
        float4 a = up[i];
        float4 g = gt[i];
        float fa[4] = {a.x, a.y, a.z, a.w};
        float fg[4] = {g.x, g.y, g.z, g.w};
        #pragma unroll
        for (int e = 0; e < 4; e++) {
            float gq = qdq_fast(fg[e], s2, inv2, -32768.f, 32767.f);
            float aq = qdq_fast(fa[e], s3, inv3, -32768.f, 32767.f);
            float mv = gq * aq;
            fg[e] = mv;
            m = fmaxf(m, fabsf(mv));
        }
        gt[i] = make_float4(fg[0], fg[1], fg[2], fg[3]);
    }
    warp_atomic_absmax(4, m);
}

// ================= 2-term scaled-code bf16 GEMM (exact) =================
// C[M,N] = s_a * sum_blk s_w[n][blk] * ( Ah_codes @ Bcodes^T + Al_codes @ Bcodes^T )
// All MMA inputs are small integers in bf16 => fp32 accumulation is exact.
// CTA 128x256, BK=64 (2 scale blocks), 3-stage cp.async, 8 warps (warp 64x64), 1 CTA/SM.
// Optional fused SiLU pass: when fuse_up != nullptr (gate GEMM), the epilogue also
// computes act = silu(qdq(up, s1)) from the already-final up buffer, stores it in
// place, and accumulates amax|act| into slot 3 — this replaces the separate p4 pass.
#define BM 128
#define BN 256
#define BK 64
#define STAGES 3
#define A_PL (BM * BK * 2)                  // 16384 per plane
#define B_PL (BN * BK * 2)                  // 32768
#define STAGE_BYTES (2 * A_PL + B_PL)       // 65536
#define GEMM_SMEM (STAGES * STAGE_BYTES)    // 196608

__device__ __forceinline__ void load_stage(
    int c, int m0, int n0, int K, int tid, uint32_t sbase,
    const __nv_bfloat16* __restrict__ Ah, const __nv_bfloat16* __restrict__ Al,
    const __nv_bfloat16* __restrict__ Bc) {
    int kk = c * BK;
    uint32_t st = sbase + (uint32_t)(c % STAGES) * STAGE_BYTES;
    int arow = tid >> 1;
    int ac0 = (tid & 1) * 4;
    size_t aoff = (size_t)(m0 + arow) * K + kk + ac0 * 8;
    uint32_t abase = st + (uint32_t)arow * 128;
    #pragma unroll
    for (int j = 0; j < 4; j++) {
        uint32_t so = (uint32_t)(((ac0 + j) ^ (arow & 7)) << 4);
        cp16(abase + so, Ah + aoff + j * 8);
        cp16(abase + A_PL + so, Al + aoff + j * 8);
    }
    const __nv_bfloat16* bg = Bc + (size_t)(n0 + tid) * K + kk;
    uint32_t bbase = st + 2 * A_PL + (uint32_t)tid * 128;
    #pragma unroll
    for (int j = 0; j < 8; j++)
        cp16(bbase + (uint32_t)((j ^ (tid & 7)) << 4), bg + j * 8);
    CP_COMMIT();
}

__global__ void __launch_bounds__(256, 1)
k_gemm_sc(const __nv_bfloat16* __restrict__ Ah, const __nv_bfloat16* __restrict__ Al,
          const __nv_bfloat16* __restrict__ Bc, const float* __restrict__ WsT,
          float* __restrict__ C, int N, int K, int slot_in, int slot_out,
          float* __restrict__ fuse_up) {
    extern __shared__ char smem[];
    const uint32_t sbase = smem_u32(smem);
    const int tid = threadIdx.x, wid = tid >> 5, lane = tid & 31;
    const int wm = wid >> 2, wn = wid & 3;          // 2 x 4 warp grid, warp tile 64x64
    const int m0 = blockIdx.y * BM, n0 = blockIdx.x * BN;
    const int chunks = K / BK;

    float facc[4][8][4];
    #pragma unroll
    for (int i = 0; i < 4; i++)
        #pragma unroll
        for (int j = 0; j < 8; j++)
            #pragma unroll
            for (int e = 0; e < 4; e++) facc[i][j][e] = 0.f;

    const int a_ro = (lane & 7) + ((lane & 8) ? 8 : 0);
    const int a_chk = (lane >> 4) & 1;
    const int b_ro = (lane & 7) + ((lane & 16) ? 8 : 0);
    const int b_chk = (lane >> 3) & 1;

    load_stage(0, m0, n0, K, tid, sbase, Ah, Al, Bc);
    load_stage(1, m0, n0, K, tid, sbase, Ah, Al, Bc);

    for (int c = 0; c < chunks; ++c) {
        if (c + 1 < chunks) asm volatile("cp.async.wait_group 1;" ::: "memory");
        else                asm volatile("cp.async.wait_group 0;" ::: "memory");
        __syncthreads();
        if (c + STAGES - 1 < chunks)
            load_stage(c + STAGES - 1, m0, n0, K, tid, sbase, Ah, Al, Bc);

        uint32_t st = sbase + (uint32_t)(c % STAGES) * STAGE_BYTES;
        uint32_t sAh = st, sAl = st + A_PL, sB = st + 2 * A_PL;

        #pragma unroll
        for (int kb = 0; kb < 2; kb++) {
            const float* wsr = WsT + (size_t)(c * 2 + kb) * N + n0 + wn * 64 + (lane & 3) * 2;
            float2 sc[8];
            #pragma unroll
            for (int j = 0; j < 8; j++) sc[j] = __ldg((const float2*)(wsr + j * 8));

            #pragma unroll
            for (int ks2 = 0; ks2 < 2; ks2++) {
                int ks = kb * 2 + ks2;
                uint32_t ah[4][4], al[4][4], bb[4][4];
                #pragma unroll
                for (int i = 0; i < 4; i++) {
                    int row = wm * 64 + i * 16 + a_ro;
                    uint32_t so = (uint32_t)(((2 * ks + a_chk) ^ (row & 7)) << 4);
                    LDSM4(ah[i], sAh + (uint32_t)row * 128 + so);
                    LDSM4(al[i], sAl + (uint32_t)row * 128 + so);
                }
                #pragma unroll
                for (int j = 0; j < 4; j++) {
                    int row = wn * 64 + j * 16 + b_ro;
                    uint32_t so = (uint32_t)(((2 * ks + b_chk) ^ (row & 7)) << 4);
                    LDSM4(bb[j], sB + (uint32_t)row * 128 + so);
                }
                #pragma unroll
                for (int i = 0; i < 4; i++)
                    #pragma unroll
                    for (int j2 = 0; j2 < 8; j2++) {
                        uint32_t b0 = bb[j2 >> 1][(j2 & 1) * 2];
                        uint32_t b1 = bb[j2 >> 1][(j2 & 1) * 2 + 1];
                        float Pb[4];
                        MMA_BF16_ZC(Pb, ah[i], b0, b1);
                        MMA_BF16_ACC(Pb, al[i], b0, b1);
                        facc[i][j2][0] = fmaf(Pb[0], sc[j2].x, facc[i][j2][0]);
                        facc[i][j2][1] = fmaf(Pb[1], sc[j2].y, facc[i][j2][1]);
                        facc[i][j2][2] = fmaf(Pb[2], sc[j2].x, facc[i][j2][2]);
                        facc[i][j2][3] = fmaf(Pb[3], sc[j2].y, facc[i][j2][3]);
                    }
            }
        }
    }

    // epilogue: scale by activation scale, store, fused absmax (+ optional fused SiLU of up)
    float s = get_scale(slot_in, 32767.f);
    const bool fuse = (fuse_up != nullptr);
    float s1 = 0.f, inv1 = 0.f;
    if (fuse) { s1 = get_scale(1, 32767.f); inv1 = 1.f / s1; }
    const int g = lane >> 2, q = lane & 3;
    float mx = 0.f, mxa = 0.f;
    #pragma unroll
    for (int i = 0; i < 4; i++) {
        #pragma unroll
        for (int j2 = 0; j2 < 8; j2++) {
            int row = m0 + wm * 64 + i * 16 + g;
            int col = n0 + wn * 64 + j2 * 8 + q * 2;
            size_t o0 = (size_t)row * N + col;
            size_t o1 = (size_t)(row + 8) * N + col;
            float v0 = facc[i][j2][0] * s, v1 = facc[i][j2][1] * s;
            float v2 = facc[i][j2][2] * s, v3 = facc[i][j2][3] * s;
            *(float2*)&C[o0] = make_float2(v0, v1);
            *(float2*)&C[o1] = make_float2(v2, v3);
            mx = fmaxf(mx, fmaxf(fmaxf(fabsf(v0), fabsf(v1)), fmaxf(fabsf(v2), fabsf(v3))));
            if (fuse) {
                float2 u0 = *(const float2*)&fuse_up[o0];
                float2 u1 = *(const float2*)&fuse_up[o1];
                float a0 = silu_of_qdq(u0.x, s1, inv1);
                float a1 = silu_of_qdq(u0.y, s1, inv1);
                float a2 = silu_of_qdq(u1.x, s1, inv1);
                float a3 = silu_of_qdq(u1.y, s1, inv1);
                *(float2*)&fuse_up[o0] = make_float2(a0, a1);
                *(float2*)&fuse_up[o1] = make_float2(a2, a3);
                mxa = fmaxf(mxa, fmaxf(fmaxf(fabsf(a0), fabsf(a1)),
                                       fmaxf(fabsf(a2), fabsf(a3))));
            }
        }
    }
    if (slot_out >= 0) warp_atomic_absmax(slot_out, mx);
    if (fuse) warp_atomic_absmax(3, mxa);
}

// ================= host =================
extern "C" void kernel_launch(void* const* d_in, const int* in_sizes, int n_in,
                              void* d_out, int out_size) {
    const float* x      = (const float*)d_in[0];
    const float* w_gate = (const float*)d_in[1];
    const float* w_up   = (const float*)d_in[2];
    const float* w_down = (const float*)d_in[3];
    float* out = (float*)d_out;

    void *p_xh, *p_xl, *p_wu, *p_wg, *p_wd, *p_wsu, *p_wsg, *p_wsd;
    void *p_mh, *p_ml, *p_up, *p_gate;
    cudaGetSymbolAddress(&p_xh, g_xh);   cudaGetSymbolAddress(&p_xl, g_xl);
    cudaGetSymbolAddress(&p_wu, g_wu);   cudaGetSymbolAddress(&p_wg, g_wg);
    cudaGetSymbolAddress(&p_wd, g_wd);
    cudaGetSymbolAddress(&p_wsu, g_wsu); cudaGetSymbolAddress(&p_wsg, g_wsg);
    cudaGetSymbolAddress(&p_wsd, g_wsd);
    cudaGetSymbolAddress(&p_mh, g_mh);   cudaGetSymbolAddress(&p_ml, g_ml);
    cudaGetSymbolAddress(&p_up, g_up);   cudaGetSymbolAddress(&p_gate, g_gate);

    static bool once = false;
    if (!once) {
        cudaFuncSetAttribute(k_gemm_sc, cudaFuncAttributeMaxDynamicSharedMemorySize, GEMM_SMEM);
        once = true;
    }

    const int GS = 1184;
    const size_t nx4 = (size_t)T_TOK * H_DIM / 4;
    const size_t nx8 = (size_t)T_TOK * H_DIM / 8;
    const size_t nti4 = (size_t)T_TOK * I_DIM / 4;
    const size_t nti8 = (size_t)T_TOK * I_DIM / 8;

    k_zero<<<1, 32>>>();
    k_absmax4<<<GS, 256>>>((const float4*)x, nx4, 0);
    k_split_bf16<<<GS, 256>>>((const float4*)x, (uint4*)p_xh, (uint4*)p_xl, nx8, 0);
    k_dqw_bf16<<<GS, 256>>>(w_up,   (uint4*)p_wu, (float*)p_wsu, I_DIM, H_DIM);
    k_dqw_bf16<<<GS, 256>>>(w_gate, (uint4*)p_wg, (float*)p_wsg, I_DIM, H_DIM);
    k_dqw_bf16<<<GS, 256>>>(w_down, (uint4*)p_wd, (float*)p_wsd, H_DIM, I_DIM);

    dim3 g1(I_DIM / BN, T_TOK / BM);   // 24 x 32
    // up GEMM: amax(up) -> slot 1
    k_gemm_sc<<<g1, 256, GEMM_SMEM>>>((const __nv_bfloat16*)p_xh, (const __nv_bfloat16*)p_xl,
                                      (const __nv_bfloat16*)p_wu, (const float*)p_wsu,
                                      (float*)p_up, I_DIM, H_DIM, 0, 1, nullptr);
    // gate GEMM: amax(gate) -> slot 2, PLUS fused act = silu(qdq(up, s1)) in-place into g_up,
    // amax(act) -> slot 3 (s1 is final because the up GEMM completed before this launch)
    k_gemm_sc<<<g1, 256, GEMM_SMEM>>>((const __nv_bfloat16*)p_xh, (const __nv_bfloat16*)p_xl,
                                      (const __nv_bfloat16*)p_wg, (const float*)p_wsg,
                                      (float*)p_gate, I_DIM, H_DIM, 0, 2, (float*)p_up);
    k_p5<<<GS, 256>>>(nti4);
    k_split_bf16<<<GS, 256>>>((const float4*)p_gate, (uint4*)p_mh, (uint4*)p_ml, nti8, 4);

    dim3 g3(H_DIM / BN, T_TOK / BM);   // 8 x 32
    k_gemm_sc<<<g3, 256, GEMM_SMEM>>>((const __nv_bfloat16*)p_mh, (const __nv_bfloat16*)p_ml,
                                      (const __nv_bfloat16*)p_wd, (const float*)p_wsd,
                                      out, H_DIM, I_DIM, 4, -1, nullptr);
}

// round 12
// speedup vs baseline: 2.9076x; 1.0750x over previous
#include <cuda_runtime.h>
#include <cuda_bf16.h>
#include <math.h>
#include <stdint.h>

#define T_TOK 4096
#define H_DIM 2048
#define I_DIM 6144

// ================= device scratch (static — no runtime alloc) =================
__device__ __align__(128) __nv_bfloat16 g_xh[(size_t)T_TOK * H_DIM];  // hi plane
__device__ __align__(128) __nv_bfloat16 g_xl[(size_t)T_TOK * H_DIM];  // lo plane
__device__ __align__(128) __nv_bfloat16 g_wu[(size_t)I_DIM * H_DIM];  // int4 codes as bf16
__device__ __align__(128) __nv_bfloat16 g_wg[(size_t)I_DIM * H_DIM];
__device__ __align__(128) __nv_bfloat16 g_wd[(size_t)H_DIM * I_DIM];
__device__ __align__(128) float g_wsu[(size_t)(H_DIM / 32) * I_DIM];  // [block][n]
__device__ __align__(128) float g_wsg[(size_t)(H_DIM / 32) * I_DIM];
__device__ __align__(128) float g_wsd[(size_t)(I_DIM / 32) * H_DIM];
__device__ __align__(128) __nv_bfloat16 g_mh[(size_t)T_TOK * I_DIM];
__device__ __align__(128) __nv_bfloat16 g_ml[(size_t)T_TOK * I_DIM];
__device__ __align__(128) float g_up[(size_t)T_TOK * I_DIM];
__device__ __align__(128) float g_gate[(size_t)T_TOK * I_DIM];
__device__ unsigned g_absmax[8]; // 0=x 1=up 2=gate 3=act 4=mid

// ================= PTX helpers =================
__device__ __forceinline__ uint32_t smem_u32(const void* p) {
    uint32_t a;
    asm("{ .reg .u64 t; cvta.to.shared.u64 t, %1; cvt.u32.u64 %0, t; }" : "=r"(a) : "l"(p));
    return a;
}
__device__ __forceinline__ void cp16(uint32_t dst, const void* src) {
    asm volatile("cp.async.cg.shared.global [%0], [%1], 16;" :: "r"(dst), "l"(src));
}
#define CP_COMMIT() asm volatile("cp.async.commit_group;" ::: "memory")

#define LDSM4(r, addr) \
    asm volatile("ldmatrix.sync.aligned.m8n8.x4.shared.b16 {%0,%1,%2,%3}, [%4];" \
        : "=r"((r)[0]), "=r"((r)[1]), "=r"((r)[2]), "=r"((r)[3]) : "r"(addr))

#define MMA_BF16_ZC(d, a, b0, b1) \
    asm volatile("mma.sync.aligned.m16n8k16.row.col.f32.bf16.bf16.f32 " \
        "{%0,%1,%2,%3},{%4,%5,%6,%7},{%8,%9},{%10,%10,%10,%10};" \
        : "=f"((d)[0]), "=f"((d)[1]), "=f"((d)[2]), "=f"((d)[3]) \
        : "r"((a)[0]), "r"((a)[1]), "r"((a)[2]), "r"((a)[3]), \
          "r"(b0), "r"(b1), "f"(0.f))

#define MMA_BF16_ACC(d, a, b0, b1) \
    asm volatile("mma.sync.aligned.m16n8k16.row.col.f32.bf16.bf16.f32 " \
        "{%0,%1,%2,%3},{%4,%5,%6,%7},{%8,%9},{%0,%1,%2,%3};" \
        : "+f"((d)[0]), "+f"((d)[1]), "+f"((d)[2]), "+f"((d)[3]) \
        : "r"((a)[0]), "r"((a)[1]), "r"((a)[2]), "r"((a)[3]), "r"(b0), "r"(b1))

__device__ __forceinline__ float get_scale(int slot, float qmax) {
    return fmaxf(__uint_as_float(g_absmax[slot]) / qmax, 1e-12f);
}
__device__ __forceinline__ void warp_atomic_absmax(int slot, float v) {
    #pragma unroll
    for (int o = 16; o; o >>= 1) v = fmaxf(v, __shfl_xor_sync(0xffffffffu, v, o));
    if ((threadIdx.x & 31) == 0) atomicMax(&g_absmax[slot], __float_as_uint(v));
}
// pack two floats into bf16x2 (lo in low 16 bits) with a single cvt
__device__ __forceinline__ uint32_t cvt_bf2(float lo, float hi) {
    uint32_t r;
    asm("cvt.rn.bf16x2.f32 %0, %1, %2;" : "=r"(r) : "f"(hi), "f"(lo));
    return r;
}
__device__ __forceinline__ float tanh_fast(float x) {
    float t;
    asm("tanh.approx.f32 %0, %1;" : "=f"(t) : "f"(x));
    return t;
}

// ================= elementwise kernels =================
__global__ void k_zero() { if (threadIdx.x < 8) g_absmax[threadIdx.x] = 0u; }

__global__ void k_absmax4(const float4* __restrict__ x, size_t n4, int slot) {
    size_t i = (size_t)blockIdx.x * blockDim.x + threadIdx.x;
    size_t st = (size_t)gridDim.x * blockDim.x;
    float m = 0.f;
    for (; i < n4; i += st) {
        float4 v = x[i];
        m = fmaxf(m, fmaxf(fmaxf(fabsf(v.x), fabsf(v.y)), fmaxf(fabsf(v.z), fabsf(v.w))));
    }
    warp_atomic_absmax(slot, m);
}

// quantize fp32 -> int16 code (no clamp needed: |q| <= 32767 by construction)
// -> exact bf16 planes hi = 256*rint(q/256), lo = q - hi (|lo| <= 128). 8 elems/thread.
__global__ void k_split_bf16(const float4* __restrict__ in, uint4* __restrict__ oh,
                             uint4* __restrict__ ol, size_t n8, int slot) {
    float s = get_scale(slot, 32767.f);
    float inv = 1.f / s;
    size_t i = (size_t)blockIdx.x * blockDim.x + threadIdx.x;
    size_t st = (size_t)gridDim.x * blockDim.x;
    for (; i < n8; i += st) {
        float4 v0 = in[2 * i], v1 = in[2 * i + 1];
        float f[8] = {v0.x, v0.y, v0.z, v0.w, v1.x, v1.y, v1.z, v1.w};
        float fh[8], fl[8];
        #pragma unroll
        for (int e = 0; e < 8; e++) {
            float q = rintf(f[e] * inv);                    // |q| <= 32767
            float qh = rintf(q * 0.00390625f) * 256.f;      // exact bf16 (mult of 256)
            fh[e] = qh;
            fl[e] = q - qh;                                 // integer in [-128,128], exact
        }
        oh[i] = make_uint4(cvt_bf2(fh[0], fh[1]), cvt_bf2(fh[2], fh[3]),
                           cvt_bf2(fh[4], fh[5]), cvt_bf2(fh[6], fh[7]));
        ol[i] = make_uint4(cvt_bf2(fl[0], fl[1]), cvt_bf2(fl[2], fl[3]),
                           cvt_bf2(fl[4], fl[5]), cvt_bf2(fl[6], fl[7]));
    }
}

// LPBQ weight: int4 codes stored as bf16 (exact, |q|<=7 by construction) + scale [b][n]
__global__ void k_dqw_bf16(const float* __restrict__ w, uint4* __restrict__ oq,
                           float* __restrict__ wsT, int N, int K) {
    int kb = K / 32;
    size_t nblk = (size_t)N * kb;
    size_t i = (size_t)blockIdx.x * blockDim.x + threadIdx.x;
    size_t st = (size_t)gridDim.x * blockDim.x;
    for (; i < nblk; i += st) {
        int n = (int)(i / kb);
        int b = (int)(i % kb);
        const float4* p = (const float4*)(w + (size_t)n * K + b * 32);
        float4 v[8];
        float m = 0.f;
        #pragma unroll
        for (int j = 0; j < 8; j++) {
            v[j] = p[j];
            m = fmaxf(m, fmaxf(fmaxf(fabsf(v[j].x), fabsf(v[j].y)),
                               fmaxf(fabsf(v[j].z), fabsf(v[j].w))));
        }
        float s = fmaxf(m / 7.0f, 1e-12f);
        float inv = 1.f / s;
        uint32_t cw[16];
        #pragma unroll
        for (int j = 0; j < 8; j++) {
            float q0 = rintf(v[j].x * inv), q1 = rintf(v[j].y * inv);
            float q2 = rintf(v[j].z * inv), q3 = rintf(v[j].w * inv);
            cw[2 * j]     = cvt_bf2(q0, q1);
            cw[2 * j + 1] = cvt_bf2(q2, q3);
        }
        uint4* dst = oq + ((size_t)n * K + b * 32) / 8;
        #pragma unroll
        for (int j = 0; j < 4; j++)
            dst[j] = make_uint4(cw[4 * j], cw[4 * j + 1], cw[4 * j + 2], cw[4 * j + 3]);
        wsT[(size_t)b * N + n] = s;
    }
}

// P4: uq = qdq(up,s1); act = silu(uq) = uq*(0.5+0.5*tanh(uq/2)) -> g_up; amax -> 3
__global__ void k_p4(size_t n4) {
    float s1 = get_scale(1, 32767.f);
    float inv1 = 1.f / s1;
    float4* up = (float4*)g_up;
    size_t i = (size_t)blockIdx.x * blockDim.x + threadIdx.x;
    size_t st = (size_t)gridDim.x * blockDim.x;
    float m = 0.f;
    for (; i < n4; i += st) {
        float4 u = up[i];
        float f[4] = {u.x, u.y, u.z, u.w};
        #pragma unroll
        for (int e = 0; e < 4; e++) {
            float uq = rintf(f[e] * inv1) * s1;
            float t = tanh_fast(0.5f * uq);
            float a = uq * fmaf(0.5f, t, 0.5f);
            f[e] = a;
            m = fmaxf(m, fabsf(a));
        }
        up[i] = make_float4(f[0], f[1], f[2], f[3]);
    }
    warp_atomic_absmax(3, m);
}

// P5: gq = qdq(gate,s2); aq = qdq(act,s3); mid = gq*aq -> g_gate; amax -> 4
__global__ void k_p5(size_t n4) {
    float s2 = get_scale(2, 32767.f);
    float inv2 = 1.f / s2;
    float s3 = get_scale(3, 32767.f);
    float inv3 = 1.f / s3;
    const float4* up = (const float4*)g_up;
    float4* gt = (float4*)g_gate;
    size_t i = (size_t)blockIdx.x * blockDim.x + threadIdx.x;
    size_t st = (size_t)gridDim.x * blockDim.x;
    float m = 0.f;
    for (; i < n4; i += st) {
        float4 a = up[i];
        float4 g = gt[i];
        float fa[4] = {a.x, a.y, a.z, a.w};
        float fg[4] = {g.x, g.y, g.z, g.w};
        #pragma unroll
        for (int e = 0; e < 4; e++) {
            float gq = rintf(fg[e] * inv2) * s2;
            float aq = rintf(fa[e] * inv3) * s3;
            float mv = gq * aq;
            fg[e] = mv;
            m = fmaxf(m, fabsf(mv));
        }
        gt[i] = make_float4(fg[0], fg[1], fg[2], fg[3]);
    }
    warp_atomic_absmax(4, m);
}

// ================= 2-term scaled-code bf16 GEMM (exact) =================
// C[M,N] = s_a * sum_blk s_w[n][blk] * ( Ah @ B^T + Al @ B^T ), exact fp32 accumulation.
// Supports a dual launch: blockIdx.x < halfX -> (B0, Ws0, C0, so0), else (B1, Ws1, C1, so1)
// — used to merge the up and gate GEMMs into one launch (shared A, one tail wave).
#define BM 128
#define BN 256
#define BK 64
#define STAGES 3
#define A_PL (BM * BK * 2)
#define B_PL (BN * BK * 2)
#define STAGE_BYTES (2 * A_PL + B_PL)       // 65536
#define GEMM_SMEM (STAGES * STAGE_BYTES)    // 196608

__device__ __forceinline__ void load_stage(
    int c, int m0, int n0, int K, int tid, uint32_t sbase,
    const __nv_bfloat16* __restrict__ Ah, const __nv_bfloat16* __restrict__ Al,
    const __nv_bfloat16* __restrict__ Bc) {
    int kk = c * BK;
    uint32_t st = sbase + (uint32_t)(c % STAGES) * STAGE_BYTES;
    int arow = tid >> 1;
    int ac0 = (tid & 1) * 4;
    size_t aoff = (size_t)(m0 + arow) * K + kk + ac0 * 8;
    uint32_t abase = st + (uint32_t)arow * 128;
    #pragma unroll
    for (int j = 0; j < 4; j++) {
        uint32_t so = (uint32_t)(((ac0 + j) ^ (arow & 7)) << 4);
        cp16(abase + so, Ah + aoff + j * 8);
        cp16(abase + A_PL + so, Al + aoff + j * 8);
    }
    const __nv_bfloat16* bg = Bc + (size_t)(n0 + tid) * K + kk;
    uint32_t bbase = st + 2 * A_PL + (uint32_t)tid * 128;
    #pragma unroll
    for (int j = 0; j < 8; j++)
        cp16(bbase + (uint32_t)((j ^ (tid & 7)) << 4), bg + j * 8);
    CP_COMMIT();
}

__global__ void __launch_bounds__(256, 1)
k_gemm_sc(const __nv_bfloat16* __restrict__ Ah, const __nv_bfloat16* __restrict__ Al,
          const __nv_bfloat16* __restrict__ B0, const float* __restrict__ Ws0,
          float* __restrict__ C0, int so0,
          const __nv_bfloat16* __restrict__ B1, const float* __restrict__ Ws1,
          float* __restrict__ C1, int so1,
          int halfX, int N, int K, int slot_in) {
    extern __shared__ char smem[];
    const uint32_t sbase = smem_u32(smem);
    const int tid = threadIdx.x, wid = tid >> 5, lane = tid & 31;
    const int wm = wid >> 2, wn = wid & 3;          // 2 x 4 warp grid, warp tile 64x64
    const bool second = ((int)blockIdx.x >= halfX);
    const int nblk = second ? ((int)blockIdx.x - halfX) : (int)blockIdx.x;
    const __nv_bfloat16* Bc = second ? B1 : B0;
    const float* WsT = second ? Ws1 : Ws0;
    float* C = second ? C1 : C0;
    const int slot_out = second ? so1 : so0;
    const int m0 = blockIdx.y * BM, n0 = nblk * BN;
    const int chunks = K / BK;

    float facc[4][8][4];
    #pragma unroll
    for (int i = 0; i < 4; i++)
        #pragma unroll
        for (int j = 0; j < 8; j++)
            #pragma unroll
            for (int e = 0; e < 4; e++) facc[i][j][e] = 0.f;

    const int a_ro = (lane & 7) + ((lane & 8) ? 8 : 0);
    const int a_chk = (lane >> 4) & 1;
    const int b_ro = (lane & 7) + ((lane & 16) ? 8 : 0);
    const int b_chk = (lane >> 3) & 1;

    load_stage(0, m0, n0, K, tid, sbase, Ah, Al, Bc);
    load_stage(1, m0, n0, K, tid, sbase, Ah, Al, Bc);

    for (int c = 0; c < chunks; ++c) {
        if (c + 1 < chunks) asm volatile("cp.async.wait_group 1;" ::: "memory");
        else                asm volatile("cp.async.wait_group 0;" ::: "memory");
        __syncthreads();
        if (c + STAGES - 1 < chunks)
            load_stage(c + STAGES - 1, m0, n0, K, tid, sbase, Ah, Al, Bc);

        uint32_t st = sbase + (uint32_t)(c % STAGES) * STAGE_BYTES;
        uint32_t sAh = st, sAl = st + A_PL, sB = st + 2 * A_PL;

        #pragma unroll
        for (int kb = 0; kb < 2; kb++) {
            const float* wsr = WsT + (size_t)(c * 2 + kb) * N + n0 + wn * 64 + (lane & 3) * 2;
            float2 sc[8];
            #pragma unroll
            for (int j = 0; j < 8; j++) sc[j] = __ldg((const float2*)(wsr + j * 8));

            #pragma unroll
            for (int ks2 = 0; ks2 < 2; ks2++) {
                int ks = kb * 2 + ks2;
                uint32_t ah[4][4], al[4][4], bb[4][4];
                #pragma unroll
                for (int i = 0; i < 4; i++) {
                    int row = wm * 64 + i * 16 + a_ro;
                    uint32_t so = (uint32_t)(((2 * ks + a_chk) ^ (row & 7)) << 4);
                    LDSM4(ah[i], sAh + (uint32_t)row * 128 + so);
                    LDSM4(al[i], sAl + (uint32_t)row * 128 + so);
                }
                #pragma unroll
                for (int j = 0; j < 4; j++) {
                    int row = wn * 64 + j * 16 + b_ro;
                    uint32_t so = (uint32_t)(((2 * ks + b_chk) ^ (row & 7)) << 4);
                    LDSM4(bb[j], sB + (uint32_t)row * 128 + so);
                }
                #pragma unroll
                for (int i = 0; i < 4; i++)
                    #pragma unroll
                    for (int j2 = 0; j2 < 8; j2++) {
                        uint32_t b0 = bb[j2 >> 1][(j2 & 1) * 2];
                        uint32_t b1 = bb[j2 >> 1][(j2 & 1) * 2 + 1];
                        float Pb[4];
                        MMA_BF16_ZC(Pb, ah[i], b0, b1);
                        MMA_BF16_ACC(Pb, al[i], b0, b1);
                        facc[i][j2][0] = fmaf(Pb[0], sc[j2].x, facc[i][j2][0]);
                        facc[i][j2][1] = fmaf(Pb[1], sc[j2].y, facc[i][j2][1]);
                        facc[i][j2][2] = fmaf(Pb[2], sc[j2].x, facc[i][j2][2]);
                        facc[i][j2][3] = fmaf(Pb[3], sc[j2].y, facc[i][j2][3]);
                    }
            }
        }
    }

    float s = get_scale(slot_in, 32767.f);
    const int g = lane >> 2, q = lane & 3;
    float mx = 0.f;
    #pragma unroll
    for (int i = 0; i < 4; i++) {
        #pragma unroll
        for (int j2 = 0; j2 < 8; j2++) {
            int row = m0 + wm * 64 + i * 16 + g;
            int col = n0 + wn * 64 + j2 * 8 + q * 2;
            float v0 = facc[i][j2][0] * s, v1 = facc[i][j2][1] * s;
            float v2 = facc[i][j2][2] * s, v3 = facc[i][j2][3] * s;
            *(float2*)&C[(size_t)row * N + col] = make_float2(v0, v1);
            *(float2*)&C[(size_t)(row + 8) * N + col] = make_float2(v2, v3);
            mx = fmaxf(mx, fmaxf(fmaxf(fabsf(v0), fabsf(v1)), fmaxf(fabsf(v2), fabsf(v3))));
        }
    }
    if (slot_out >= 0) warp_atomic_absmax(slot_out, mx);
}

// ================= host =================
extern "C" void kernel_launch(void* const* d_in, const int* in_sizes, int n_in,
                              void* d_out, int out_size) {
    const float* x      = (const float*)d_in[0];
    const float* w_gate = (const float*)d_in[1];
    const float* w_up   = (const float*)d_in[2];
    const float* w_down = (const float*)d_in[3];
    float* out = (float*)d_out;

    void *p_xh, *p_xl, *p_wu, *p_wg, *p_wd, *p_wsu, *p_wsg, *p_wsd;
    void *p_mh, *p_ml, *p_up, *p_gate;
    cudaGetSymbolAddress(&p_xh, g_xh);   cudaGetSymbolAddress(&p_xl, g_xl);
    cudaGetSymbolAddress(&p_wu, g_wu);   cudaGetSymbolAddress(&p_wg, g_wg);
    cudaGetSymbolAddress(&p_wd, g_wd);
    cudaGetSymbolAddress(&p_wsu, g_wsu); cudaGetSymbolAddress(&p_wsg, g_wsg);
    cudaGetSymbolAddress(&p_wsd, g_wsd);
    cudaGetSymbolAddress(&p_mh, g_mh);   cudaGetSymbolAddress(&p_ml, g_ml);
    cudaGetSymbolAddress(&p_up, g_up);   cudaGetSymbolAddress(&p_gate, g_gate);

    static bool once = false;
    if (!once) {
        cudaFuncSetAttribute(k_gemm_sc, cudaFuncAttributeMaxDynamicSharedMemorySize, GEMM_SMEM);
        once = true;
    }

    const int GS = 1184;
    const size_t nx4 = (size_t)T_TOK * H_DIM / 4;
    const size_t nx8 = (size_t)T_TOK * H_DIM / 8;
    const size_t nti4 = (size_t)T_TOK * I_DIM / 4;
    const size_t nti8 = (size_t)T_TOK * I_DIM / 8;

    k_zero<<<1, 32>>>();
    k_absmax4<<<GS, 256>>>((const float4*)x, nx4, 0);
    k_split_bf16<<<GS, 256>>>((const float4*)x, (uint4*)p_xh, (uint4*)p_xl, nx8, 0);
    k_dqw_bf16<<<GS, 256>>>(w_up,   (uint4*)p_wu, (float*)p_wsu, I_DIM, H_DIM);
    k_dqw_bf16<<<GS, 256>>>(w_gate, (uint4*)p_wg, (float*)p_wsg, I_DIM, H_DIM);
    k_dqw_bf16<<<GS, 256>>>(w_down, (uint4*)p_wd, (float*)p_wsd, H_DIM, I_DIM);

    // merged up+gate GEMM: x-blocks [0,24) -> up (slot 1), [24,48) -> gate (slot 2)
    dim3 g1(2 * (I_DIM / BN), T_TOK / BM);   // 48 x 32
    k_gemm_sc<<<g1, 256, GEMM_SMEM>>>(
        (const __nv_bfloat16*)p_xh, (const __nv_bfloat16*)p_xl,
        (const __nv_bfloat16*)p_wu, (const float*)p_wsu, (float*)p_up, 1,
        (const __nv_bfloat16*)p_wg, (const float*)p_wsg, (float*)p_gate, 2,
        I_DIM / BN, I_DIM, H_DIM, 0);

    k_p4<<<GS, 256>>>(nti4);
    k_p5<<<GS, 256>>>(nti4);
    k_split_bf16<<<GS, 256>>>((const float4*)p_gate, (uint4*)p_mh, (uint4*)p_ml, nti8, 4);

    dim3 g3(H_DIM / BN, T_TOK / BM);   // 8 x 32
    k_gemm_sc<<<g3, 256, GEMM_SMEM>>>(
        (const __nv_bfloat16*)p_mh, (const __nv_bfloat16*)p_ml,
        (const __nv_bfloat16*)p_wd, (const float*)p_wsd, out, -1,
        (const __nv_bfloat16*)p_wd, (const float*)p_wsd, out, -1,
        H_DIM / BN, H_DIM, I_DIM, 4);
}

// round 13
// speedup vs baseline: 2.9488x; 1.0142x over previous
#include <cuda_runtime.h>
#include <cuda_bf16.h>
#include <math.h>
#include <stdint.h>

#define T_TOK 4096
#define H_DIM 2048
#define I_DIM 6144

// ================= device scratch (static — no runtime alloc) =================
__device__ __align__(128) __nv_bfloat16 g_xh[(size_t)T_TOK * H_DIM];  // hi plane
__device__ __align__(128) __nv_bfloat16 g_xl[(size_t)T_TOK * H_DIM];  // lo plane
__device__ __align__(128) __nv_bfloat16 g_wu[(size_t)I_DIM * H_DIM];  // int4 codes as bf16
__device__ __align__(128) __nv_bfloat16 g_wg[(size_t)I_DIM * H_DIM];
__device__ __align__(128) __nv_bfloat16 g_wd[(size_t)H_DIM * I_DIM];
__device__ __align__(128) float g_wsu[(size_t)(H_DIM / 32) * I_DIM];  // [block][n]
__device__ __align__(128) float g_wsg[(size_t)(H_DIM / 32) * I_DIM];
__device__ __align__(128) float g_wsd[(size_t)(I_DIM / 32) * H_DIM];
__device__ __align__(128) __nv_bfloat16 g_mh[(size_t)T_TOK * I_DIM];
__device__ __align__(128) __nv_bfloat16 g_ml[(size_t)T_TOK * I_DIM];
__device__ __align__(128) float g_up[(size_t)T_TOK * I_DIM];    // raw up (kept raw)
__device__ __align__(128) float g_gate[(size_t)T_TOK * I_DIM];  // gate raw -> mid
__device__ unsigned g_absmax[8]; // 0=x 1=|up| 2=|gate| 4=|mid| 5=max+(up)

// trough of |silu| on x<0 (max of -silu there); positive branch dominates in practice
#define SILU_TROUGH 0.27846455f

// ================= PTX helpers =================
__device__ __forceinline__ uint32_t smem_u32(const void* p) {
    uint32_t a;
    asm("{ .reg .u64 t; cvta.to.shared.u64 t, %1; cvt.u32.u64 %0, t; }" : "=r"(a) : "l"(p));
    return a;
}
__device__ __forceinline__ void cp16(uint32_t dst, const void* src) {
    asm volatile("cp.async.cg.shared.global [%0], [%1], 16;" :: "r"(dst), "l"(src));
}
#define CP_COMMIT() asm volatile("cp.async.commit_group;" ::: "memory")

#define LDSM4(r, addr) \
    asm volatile("ldmatrix.sync.aligned.m8n8.x4.shared.b16 {%0,%1,%2,%3}, [%4];" \
        : "=r"((r)[0]), "=r"((r)[1]), "=r"((r)[2]), "=r"((r)[3]) : "r"(addr))

#define MMA_BF16_ZC(d, a, b0, b1) \
    asm volatile("mma.sync.aligned.m16n8k16.row.col.f32.bf16.bf16.f32 " \
        "{%0,%1,%2,%3},{%4,%5,%6,%7},{%8,%9},{%10,%10,%10,%10};" \
        : "=f"((d)[0]), "=f"((d)[1]), "=f"((d)[2]), "=f"((d)[3]) \
        : "r"((a)[0]), "r"((a)[1]), "r"((a)[2]), "r"((a)[3]), \
          "r"(b0), "r"(b1), "f"(0.f))

#define MMA_BF16_ACC(d, a, b0, b1) \
    asm volatile("mma.sync.aligned.m16n8k16.row.col.f32.bf16.bf16.f32 " \
        "{%0,%1,%2,%3},{%4,%5,%6,%7},{%8,%9},{%0,%1,%2,%3};" \
        : "+f"((d)[0]), "+f"((d)[1]), "+f"((d)[2]), "+f"((d)[3]) \
        : "r"((a)[0]), "r"((a)[1]), "r"((a)[2]), "r"((a)[3]), "r"(b0), "r"(b1))

__device__ __forceinline__ float get_scale(int slot, float qmax) {
    return fmaxf(__uint_as_float(g_absmax[slot]) / qmax, 1e-12f);
}
__device__ __forceinline__ void warp_atomic_absmax(int slot, float v) {
    #pragma unroll
    for (int o = 16; o; o >>= 1) v = fmaxf(v, __shfl_xor_sync(0xffffffffu, v, o));
    if ((threadIdx.x & 31) == 0) atomicMax(&g_absmax[slot], __float_as_uint(v));
}
__device__ __forceinline__ uint32_t cvt_bf2(float lo, float hi) {
    uint32_t r;
    asm("cvt.rn.bf16x2.f32 %0, %1, %2;" : "=r"(r) : "f"(hi), "f"(lo));
    return r;
}
__device__ __forceinline__ float tanh_fast(float x) {
    float t;
    asm("tanh.approx.f32 %0, %1;" : "=f"(t) : "f"(x));
    return t;
}
__device__ __forceinline__ float silu_fast(float x) {
    float t = tanh_fast(0.5f * x);
    return x * fmaf(0.5f, t, 0.5f);
}

// ================= elementwise kernels =================
__global__ void k_zero() { if (threadIdx.x < 8) g_absmax[threadIdx.x] = 0u; }

__global__ void k_absmax4(const float4* __restrict__ x, size_t n4, int slot) {
    size_t i = (size_t)blockIdx.x * blockDim.x + threadIdx.x;
    size_t st = (size_t)gridDim.x * blockDim.x;
    float m = 0.f;
    for (; i < n4; i += st) {
        float4 v = x[i];
        m = fmaxf(m, fmaxf(fmaxf(fabsf(v.x), fabsf(v.y)), fmaxf(fabsf(v.z), fabsf(v.w))));
    }
    warp_atomic_absmax(slot, m);
}

// quantize fp32 -> int16 code (clamp-free: |q| <= 32767 by construction)
// -> exact bf16 planes hi = 256*rint(q/256), lo = q - hi. 8 elems/thread.
__global__ void k_split_bf16(const float4* __restrict__ in, uint4* __restrict__ oh,
                             uint4* __restrict__ ol, size_t n8, int slot) {
    float s = get_scale(slot, 32767.f);
    float inv = 1.f / s;
    size_t i = (size_t)blockIdx.x * blockDim.x + threadIdx.x;
    size_t st = (size_t)gridDim.x * blockDim.x;
    for (; i < n8; i += st) {
        float4 v0 = in[2 * i], v1 = in[2 * i + 1];
        float f[8] = {v0.x, v0.y, v0.z, v0.w, v1.x, v1.y, v1.z, v1.w};
        float fh[8], fl[8];
        #pragma unroll
        for (int e = 0; e < 8; e++) {
            float q = rintf(f[e] * inv);
            float qh = rintf(q * 0.00390625f) * 256.f;
            fh[e] = qh;
            fl[e] = q - qh;
        }
        oh[i] = make_uint4(cvt_bf2(fh[0], fh[1]), cvt_bf2(fh[2], fh[3]),
                           cvt_bf2(fh[4], fh[5]), cvt_bf2(fh[6], fh[7]));
        ol[i] = make_uint4(cvt_bf2(fl[0], fl[1]), cvt_bf2(fl[2], fl[3]),
                           cvt_bf2(fl[4], fl[5]), cvt_bf2(fl[6], fl[7]));
    }
}

// merged LPBQ weight dequant for all three weights (3 equal segments of N*K/32 blocks)
__global__ void k_dqw_all(const float* __restrict__ wu, const float* __restrict__ wg,
                          const float* __restrict__ wd,
                          uint4* __restrict__ ou, uint4* __restrict__ og,
                          uint4* __restrict__ od,
                          float* __restrict__ su, float* __restrict__ sg,
                          float* __restrict__ sd) {
    const size_t NB = (size_t)I_DIM * H_DIM / 32;   // identical for all three
    size_t i = (size_t)blockIdx.x * blockDim.x + threadIdx.x;
    size_t st = (size_t)gridDim.x * blockDim.x;
    for (; i < 3 * NB; i += st) {
        int seg = (int)(i / NB);
        size_t r = i - (size_t)seg * NB;
        const float* w; uint4* oq; float* ws; int N, K;
        if (seg == 0)      { w = wu; oq = ou; ws = su; N = I_DIM; K = H_DIM; }
        else if (seg == 1) { w = wg; oq = og; ws = sg; N = I_DIM; K = H_DIM; }
        else               { w = wd; oq = od; ws = sd; N = H_DIM; K = I_DIM; }
        int kb = K / 32;
        int n = (int)(r / kb);
        int b = (int)(r % kb);
        const float4* p = (const float4*)(w + (size_t)n * K + b * 32);
        float4 v[8];
        float m = 0.f;
        #pragma unroll
        for (int j = 0; j < 8; j++) {
            v[j] = p[j];
            m = fmaxf(m, fmaxf(fmaxf(fabsf(v[j].x), fabsf(v[j].y)),
                               fmaxf(fabsf(v[j].z), fabsf(v[j].w))));
        }
        float s = fmaxf(m / 7.0f, 1e-12f);
        float inv = 1.f / s;
        uint32_t cw[16];
        #pragma unroll
        for (int j = 0; j < 8; j++) {
            float q0 = rintf(v[j].x * inv), q1 = rintf(v[j].y * inv);
            float q2 = rintf(v[j].z * inv), q3 = rintf(v[j].w * inv);
            cw[2 * j]     = cvt_bf2(q0, q1);
            cw[2 * j + 1] = cvt_bf2(q2, q3);
        }
        uint4* dst = oq + ((size_t)n * K + b * 32) / 8;
        #pragma unroll
        for (int j = 0; j < 4; j++)
            dst[j] = make_uint4(cw[4 * j], cw[4 * j + 1], cw[4 * j + 2], cw[4 * j + 3]);
        ws[(size_t)b * N + n] = s;
    }
}

// fused act+mul: s3 derived analytically from slot5 (signed max of up) & slot1.
// act = silu(qdq(up,s1)); aq = qdq(act,s3); gq = qdq(gate,s2); mid = gq*aq; amax->4.
__global__ void k_actmul(size_t n4) {
    float s1 = get_scale(1, 32767.f);
    float inv1 = 1.f / s1;
    float s2 = get_scale(2, 32767.f);
    float inv2 = 1.f / s2;
    // analytic amax|act|: silu monotone for x>0; bounded by trough for x<0
    float maxpos = __uint_as_float(g_absmax[5]);
    float uqm = rintf(maxpos * inv1) * s1;
    float amax_act = fmaxf(silu_fast(uqm), SILU_TROUGH);
    float s3 = fmaxf(amax_act / 32767.f, 1e-12f);
    float inv3 = 1.f / s3;

    const float4* up = (const float4*)g_up;
    float4* gt = (float4*)g_gate;
    size_t i = (size_t)blockIdx.x * blockDim.x + threadIdx.x;
    size_t st = (size_t)gridDim.x * blockDim.x;
    float m = 0.f;
    for (; i < n4; i += st) {
        float4 u = up[i];
        float4 g = gt[i];
        float fu[4] = {u.x, u.y, u.z, u.w};
        float fg[4] = {g.x, g.y, g.z, g.w};
        #pragma unroll
        for (int e = 0; e < 4; e++) {
            float uq = rintf(fu[e] * inv1) * s1;
            float a = silu_fast(uq);
            float aq = rintf(a * inv3) * s3;
            float gq = rintf(fg[e] * inv2) * s2;
            float mv = gq * aq;
            fg[e] = mv;
            m = fmaxf(m, fabsf(mv));
        }
        gt[i] = make_float4(fg[0], fg[1], fg[2], fg[3]);
    }
    warp_atomic_absmax(4, m);
}

// ================= 2-term scaled-code bf16 GEMM (exact) =================
// C[M,N] = s_a * sum_blk s_w[n][blk] * ( Ah @ B^T + Al @ B^T ), exact fp32 accumulation.
// Dual launch: blockIdx.x < halfX -> (B0, Ws0, C0, so0), else (B1, Ws1, C1, so1).
// When slot_out == 1 (up GEMM) the epilogue also tracks the signed positive max
// of the outputs into slot 5 (used for the analytic act scale).
#define BM 128
#define BN 256
#define BK 64
#define STAGES 3
#define A_PL (BM * BK * 2)
#define B_PL (BN * BK * 2)
#define STAGE_BYTES (2 * A_PL + B_PL)       // 65536
#define GEMM_SMEM (STAGES * STAGE_BYTES)    // 196608

__device__ __forceinline__ void load_stage(
    int c, int m0, int n0, int K, int tid, uint32_t sbase,
    const __nv_bfloat16* __restrict__ Ah, const __nv_bfloat16* __restrict__ Al,
    const __nv_bfloat16* __restrict__ Bc) {
    int kk = c * BK;
    uint32_t st = sbase + (uint32_t)(c % STAGES) * STAGE_BYTES;
    int arow = tid >> 1;
    int ac0 = (tid & 1) * 4;
    size_t aoff = (size_t)(m0 + arow) * K + kk + ac0 * 8;
    uint32_t abase = st + (uint32_t)arow * 128;
    #pragma unroll
    for (int j = 0; j < 4; j++) {
        uint32_t so = (uint32_t)(((ac0 + j) ^ (arow & 7)) << 4);
        cp16(abase + so, Ah + aoff + j * 8);
        cp16(abase + A_PL + so, Al + aoff + j * 8);
    }
    const __nv_bfloat16* bg = Bc + (size_t)(n0 + tid) * K + kk;
    uint32_t bbase = st + 2 * A_PL + (uint32_t)tid * 128;
    #pragma unroll
    for (int j = 0; j < 8; j++)
        cp16(bbase + (uint32_t)((j ^ (tid & 7)) << 4), bg + j * 8);
    CP_COMMIT();
}

__global__ void __launch_bounds__(256, 1)
k_gemm_sc(const __nv_bfloat16* __restrict__ Ah, const __nv_bfloat16* __restrict__ Al,
          const __nv_bfloat16* __restrict__ B0, const float* __restrict__ Ws0,
          float* __restrict__ C0, int so0,
          const __nv_bfloat16* __restrict__ B1, const float* __restrict__ Ws1,
          float* __restrict__ C1, int so1,
          int halfX, int N, int K, int slot_in) {
    extern __shared__ char smem[];
    const uint32_t sbase = smem_u32(smem);
    const int tid = threadIdx.x, wid = tid >> 5, lane = tid & 31;
    const int wm = wid >> 2, wn = wid & 3;
    const bool second = ((int)blockIdx.x >= halfX);
    const int nblk = second ? ((int)blockIdx.x - halfX) : (int)blockIdx.x;
    const __nv_bfloat16* Bc = second ? B1 : B0;
    const float* WsT = second ? Ws1 : Ws0;
    float* C = second ? C1 : C0;
    const int slot_out = second ? so1 : so0;
    const int m0 = blockIdx.y * BM, n0 = nblk * BN;
    const int chunks = K / BK;

    float facc[4][8][4];
    #pragma unroll
    for (int i = 0; i < 4; i++)
        #pragma unroll
        for (int j = 0; j < 8; j++)
            #pragma unroll
            for (int e = 0; e < 4; e++) facc[i][j][e] = 0.f;

    const int a_ro = (lane & 7) + ((lane & 8) ? 8 : 0);
    const int a_chk = (lane >> 4) & 1;
    const int b_ro = (lane & 7) + ((lane & 16) ? 8 : 0);
    const int b_chk = (lane >> 3) & 1;

    load_stage(0, m0, n0, K, tid, sbase, Ah, Al, Bc);
    load_stage(1, m0, n0, K, tid, sbase, Ah, Al, Bc);

    for (int c = 0; c < chunks; ++c) {
        if (c + 1 < chunks) asm volatile("cp.async.wait_group 1;" ::: "memory");
        else                asm volatile("cp.async.wait_group 0;" ::: "memory");
        __syncthreads();
        if (c + STAGES - 1 < chunks)
            load_stage(c + STAGES - 1, m0, n0, K, tid, sbase, Ah, Al, Bc);

        uint32_t st = sbase + (uint32_t)(c % STAGES) * STAGE_BYTES;
        uint32_t sAh = st, sAl = st + A_PL, sB = st + 2 * A_PL;

        #pragma unroll
        for (int kb = 0; kb < 2; kb++) {
            const float* wsr = WsT + (size_t)(c * 2 + kb) * N + n0 + wn * 64 + (lane & 3) * 2;
            float2 sc[8];
            #pragma unroll
            for (int j = 0; j < 8; j++) sc[j] = __ldg((const float2*)(wsr + j * 8));

            #pragma unroll
            for (int ks2 = 0; ks2 < 2; ks2++) {
                int ks = kb * 2 + ks2;
                uint32_t ah[4][4], al[4][4], bb[4][4];
                #pragma unroll
                for (int i = 0; i < 4; i++) {
                    int row = wm * 64 + i * 16 + a_ro;
                    uint32_t so = (uint32_t)(((2 * ks + a_chk) ^ (row & 7)) << 4);
                    LDSM4(ah[i], sAh + (uint32_t)row * 128 + so);
                    LDSM4(al[i], sAl + (uint32_t)row * 128 + so);
                }
                #pragma unroll
                for (int j = 0; j < 4; j++) {
                    int row = wn * 64 + j * 16 + b_ro;
                    uint32_t so = (uint32_t)(((2 * ks + b_chk) ^ (row & 7)) << 4);
                    LDSM4(bb[j], sB + (uint32_t)row * 128 + so);
                }
                #pragma unroll
                for (int i = 0; i < 4; i++)
                    #pragma unroll
                    for (int j2 = 0; j2 < 8; j2++) {
                        uint32_t b0 = bb[j2 >> 1][(j2 & 1) * 2];
                        uint32_t b1 = bb[j2 >> 1][(j2 & 1) * 2 + 1];
                        float Pb[4];
                        MMA_BF16_ZC(Pb, ah[i], b0, b1);
                        MMA_BF16_ACC(Pb, al[i], b0, b1);
                        facc[i][j2][0] = fmaf(Pb[0], sc[j2].x, facc[i][j2][0]);
                        facc[i][j2][1] = fmaf(Pb[1], sc[j2].y, facc[i][j2][1]);
                        facc[i][j2][2] = fmaf(Pb[2], sc[j2].x, facc[i][j2][2]);
                        facc[i][j2][3] = fmaf(Pb[3], sc[j2].y, facc[i][j2][3]);
                    }
            }
        }
    }

    float s = get_scale(slot_in, 32767.f);
    const int g = lane >> 2, q = lane & 3;
    float mx = 0.f, mpos = 0.f;
    #pragma unroll
    for (int i = 0; i < 4; i++) {
        #pragma unroll
        for (int j2 = 0; j2 < 8; j2++) {
            int row = m0 + wm * 64 + i * 16 + g;
            int col = n0 + wn * 64 + j2 * 8 + q * 2;
            float v0 = facc[i][j2][0] * s, v1 = facc[i][j2][1] * s;
            float v2 = facc[i][j2][2] * s, v3 = facc[i][j2][3] * s;
            *(float2*)&C[(size_t)row * N + col] = make_float2(v0, v1);
            *(float2*)&C[(size_t)(row + 8) * N + col] = make_float2(v2, v3);
            mx = fmaxf(mx, fmaxf(fmaxf(fabsf(v0), fabsf(v1)), fmaxf(fabsf(v2), fabsf(v3))));
            mpos = fmaxf(mpos, fmaxf(fmaxf(v0, v1), fmaxf(v2, v3)));
        }
    }
    if (slot_out >= 0) warp_atomic_absmax(slot_out, mx);
    if (slot_out == 1) warp_atomic_absmax(5, fmaxf(mpos, 0.f));
}

// ================= host =================
extern "C" void kernel_launch(void* const* d_in, const int* in_sizes, int n_in,
                              void* d_out, int out_size) {
    const float* x      = (const float*)d_in[0];
    const float* w_gate = (const float*)d_in[1];
    const float* w_up   = (const float*)d_in[2];
    const float* w_down = (const float*)d_in[3];
    float* out = (float*)d_out;

    void *p_xh, *p_xl, *p_wu, *p_wg, *p_wd, *p_wsu, *p_wsg, *p_wsd;
    void *p_mh, *p_ml, *p_up, *p_gate;
    cudaGetSymbolAddress(&p_xh, g_xh);   cudaGetSymbolAddress(&p_xl, g_xl);
    cudaGetSymbolAddress(&p_wu, g_wu);   cudaGetSymbolAddress(&p_wg, g_wg);
    cudaGetSymbolAddress(&p_wd, g_wd);
    cudaGetSymbolAddress(&p_wsu, g_wsu); cudaGetSymbolAddress(&p_wsg, g_wsg);
    cudaGetSymbolAddress(&p_wsd, g_wsd);
    cudaGetSymbolAddress(&p_mh, g_mh);   cudaGetSymbolAddress(&p_ml, g_ml);
    cudaGetSymbolAddress(&p_up, g_up);   cudaGetSymbolAddress(&p_gate, g_gate);

    static bool once = false;
    if (!once) {
        cudaFuncSetAttribute(k_gemm_sc, cudaFuncAttributeMaxDynamicSharedMemorySize, GEMM_SMEM);
        once = true;
    }

    const int GS = 1184;
    const size_t nx4 = (size_t)T_TOK * H_DIM / 4;
    const size_t nx8 = (size_t)T_TOK * H_DIM / 8;
    const size_t nti4 = (size_t)T_TOK * I_DIM / 4;
    const size_t nti8 = (size_t)T_TOK * I_DIM / 8;

    k_zero<<<1, 32>>>();
    k_absmax4<<<GS, 256>>>((const float4*)x, nx4, 0);
    k_split_bf16<<<GS, 256>>>((const float4*)x, (uint4*)p_xh, (uint4*)p_xl, nx8, 0);
    k_dqw_all<<<GS, 256>>>(w_up, w_gate, w_down,
                           (uint4*)p_wu, (uint4*)p_wg, (uint4*)p_wd,
                           (float*)p_wsu, (float*)p_wsg, (float*)p_wsd);

    // merged up+gate GEMM: x-blocks [0,24) -> up (slot 1 + pos-max slot 5), [24,48) -> gate
    dim3 g1(2 * (I_DIM / BN), T_TOK / BM);   // 48 x 32
    k_gemm_sc<<<g1, 256, GEMM_SMEM>>>(
        (const __nv_bfloat16*)p_xh, (const __nv_bfloat16*)p_xl,
        (const __nv_bfloat16*)p_wu, (const float*)p_wsu, (float*)p_up, 1,
        (const __nv_bfloat16*)p_wg, (const float*)p_wsg, (float*)p_gate, 2,
        I_DIM / BN, I_DIM, H_DIM, 0);

    // fused act+mul (p4+p5 merged; s3 derived analytically from slots 1 & 5)
    k_actmul<<<GS, 256>>>(nti4);
    k_split_bf16<<<GS, 256>>>((const float4*)p_gate, (uint4*)p_mh, (uint4*)p_ml, nti8, 4);

    dim3 g3(H_DIM / BN, T_TOK / BM);   // 8 x 32
    k_gemm_sc<<<g3, 256, GEMM_SMEM>>>(
        (const __nv_bfloat16*)p_mh, (const __nv_bfloat16*)p_ml,
        (const __nv_bfloat16*)p_wd, (const float*)p_wsd, out, -1,
        (const __nv_bfloat16*)p_wd, (const float*)p_wsd, out, -1,
        H_DIM / BN, H_DIM, I_DIM, 4);
}